// round 16
// baseline (speedup 1.0000x reference)
#include <cuda_runtime.h>

#define IMG_H 1080
#define IMG_W 1920
#define TILE_W 128
#define TILE_H 8
#define RW (TILE_W + 4)   // 132 region cols (halo 2 each side)
#define RH (TILE_H + 4)   // 12 region rows
#define NPLANE (RH * RW)  // 1584 floats per plane

__global__ __launch_bounds__(256)
void jbf_kernel(const float* __restrict__ tpl,
                const float* __restrict__ vec,
                float* __restrict__ out)
{
    __shared__ float sT0[NPLANE];
    __shared__ float sT1[NPLANE];
    __shared__ float sT2[NPLANE];
    __shared__ float sQ [NPLANE];   // -50 * (t0^2 + t1^2 + t2^2) per cell
    __shared__ float sV0[NPLANE];
    __shared__ float sV1[NPLANE];

    const int tx = threadIdx.x;          // 0..31
    const int ty = threadIdx.y;          // 0..7
    const int tid = ty * 32 + tx;        // 0..255
    const int x0 = blockIdx.x * TILE_W;
    const int y0 = blockIdx.y * TILE_H;

    const float* __restrict__ t0 = tpl;
    const float* __restrict__ t1 = tpl + IMG_H * IMG_W;
    const float* __restrict__ t2 = tpl + 2 * IMG_H * IMG_W;
    const float* __restrict__ v0 = vec;
    const float* __restrict__ v1 = vec + IMG_H * IMG_W;

    // ---- cooperative fill of the haloed region (zero-pad OOB) ----
    #pragma unroll 7
    for (int i = tid; i < NPLANE; i += 256) {
        int rr = i / RW;
        int cc = i - rr * RW;
        int gy = y0 - 2 + rr;
        int gx = x0 - 2 + cc;
        bool inb = ((unsigned)gy < IMG_H) && ((unsigned)gx < IMG_W);
        int g = inb ? (gy * IMG_W + gx) : 0;
        float x0v = inb ? __ldg(t0 + g) : 0.0f;
        float x1v = inb ? __ldg(t1 + g) : 0.0f;
        float x2v = inb ? __ldg(t2 + g) : 0.0f;
        sT0[i] = x0v;
        sT1[i] = x1v;
        sT2[i] = x2v;
        float qq = x0v * x0v;
        qq = fmaf(x1v, x1v, qq);
        qq = fmaf(x2v, x2v, qq);
        sQ[i] = -50.0f * qq;
        sV0[i] = inb ? __ldg(v0 + g) : 0.0f;
        sV1[i] = inb ? __ldg(v1 + g) : 0.0f;
    }
    __syncthreads();

    // ---- each thread computes 4 consecutive output pixels ----
    const int bcol = tx * 4;                 // smem base col of 8-float window
    const int ccol = bcol + 2;               // smem col of first center pixel

    float c0[4], c1[4], c2[4], baseC[4];
    #pragma unroll
    for (int p = 0; p < 4; p++) {
        int s = (ty + 2) * RW + ccol + p;
        c0[p] = sT0[s];
        c1[p] = sT1[s];
        c2[p] = sT2[s];
        // Tc = sum of squares of center; baseC = 0.875 - 50*Tc
        float tc = c0[p] * c0[p];
        tc = fmaf(c1[p], c1[p], tc);
        tc = fmaf(c2[p], c2[p], tc);
        baseC[p] = fmaf(tc, -50.0f, 0.875f);
    }

    float num0[4] = {0.f, 0.f, 0.f, 0.f};
    float num1[4] = {0.f, 0.f, 0.f, 0.f};
    float den[4]  = {0.f, 0.f, 0.f, 0.f};

    #pragma unroll
    for (int r = 0; r < 5; r++) {            // tap row: dy = r - 2
        const int base = (ty + r) * RW + bcol;

        float a[8], b[8], c[8], q[8], va[8], vb[8];
        *(float4*)&a[0]  = *(const float4*)&sT0[base];
        *(float4*)&a[4]  = *(const float4*)&sT0[base + 4];
        *(float4*)&b[0]  = *(const float4*)&sT1[base];
        *(float4*)&b[4]  = *(const float4*)&sT1[base + 4];
        *(float4*)&c[0]  = *(const float4*)&sT2[base];
        *(float4*)&c[4]  = *(const float4*)&sT2[base + 4];
        *(float4*)&q[0]  = *(const float4*)&sQ[base];
        *(float4*)&q[4]  = *(const float4*)&sQ[base + 4];
        *(float4*)&va[0] = *(const float4*)&sV0[base];
        *(float4*)&va[4] = *(const float4*)&sV0[base + 4];
        *(float4*)&vb[0] = *(const float4*)&sV1[base];
        *(float4*)&vb[4] = *(const float4*)&sV1[base + 4];

        #pragma unroll
        for (int dx = 0; dx < 5; dx++) {
            #pragma unroll
            for (int p = 0; p < 4; p++) {
                const int j = dx + p;
                // s = dot(center, tap) over 3 template channels
                float s = c0[p] * a[j];
                s = fmaf(c1[p], b[j], s);
                s = fmaf(c2[p], c[j], s);
                // w = max(0.875 - 50*d, 0),  d = Tc + Qtap - 2s
                //   = max(100*s + (Q'[j] + baseC), 0)
                float t = q[j] + baseC[p];
                float w = fmaf(s, 100.0f, t);
                w = fmaxf(w, 0.0f);
                den[p]  += w;
                num0[p]  = fmaf(w, va[j], num0[p]);
                num1[p]  = fmaf(w, vb[j], num1[p]);
            }
        }
    }

    // ---- normalize and store as float32, 16B coalesced per plane ----
    const int gy = y0 + ty;
    const int gx = x0 + bcol;

    float4 r0, r1;
    {
        float inv0 = 1.0f / den[0];
        float inv1 = 1.0f / den[1];
        float inv2 = 1.0f / den[2];
        float inv3 = 1.0f / den[3];
        r0 = make_float4(num0[0] * inv0, num0[1] * inv1, num0[2] * inv2, num0[3] * inv3);
        r1 = make_float4(num1[0] * inv0, num1[1] * inv1, num1[2] * inv2, num1[3] * inv3);
    }

    *reinterpret_cast<float4*>(out + (size_t)gy * IMG_W + gx) = r0;
    *reinterpret_cast<float4*>(out + (size_t)IMG_H * IMG_W + (size_t)gy * IMG_W + gx) = r1;
}

extern "C" void kernel_launch(void* const* d_in, const int* in_sizes, int n_in,
                              void* d_out, int out_size)
{
    // Bind by size: largest = template (3*H*W), second-largest = vector (2*H*W).
    int big0 = -1, big1 = -1;
    for (int i = 0; i < n_in; i++) {
        if (big0 < 0 || in_sizes[i] > in_sizes[big0]) { big1 = big0; big0 = i; }
        else if (big1 < 0 || in_sizes[i] > in_sizes[big1]) { big1 = i; }
    }
    if (big1 < 0) big1 = big0;

    const float* tpl = (const float*)d_in[big0];
    const float* vec = (const float*)d_in[big1];
    float* out = (float*)d_out;               // OUTPUT IS FLOAT32

    dim3 block(32, 8);
    dim3 grid(IMG_W / TILE_W, IMG_H / TILE_H);  // 15 x 135, exact tiling
    jbf_kernel<<<grid, block>>>(tpl, vec, out);
}

// round 17
// speedup vs baseline: 1.0258x; 1.0258x over previous
#include <cuda_runtime.h>

#define IMG_H 1080
#define IMG_W 1920
#define TILE_W 128
#define TILE_H 8
#define RW (TILE_W + 4)   // 132 region cols (halo 2 each side)
#define RH (TILE_H + 4)   // 12 region rows
#define NPLANE (RH * RW)  // 1584 floats per plane
#define SQ50 7.0710678118654755f   // sqrt(50)

__global__ __launch_bounds__(256)
void jbf_kernel(const float* __restrict__ tpl,
                const float* __restrict__ vec,
                float* __restrict__ out)
{
    __shared__ float sT0[NPLANE];   // template channels pre-scaled by sqrt(50)
    __shared__ float sT1[NPLANE];
    __shared__ float sT2[NPLANE];
    __shared__ float sV0[NPLANE];
    __shared__ float sV1[NPLANE];

    const int tx = threadIdx.x;          // 0..31
    const int ty = threadIdx.y;          // 0..7
    const int tid = ty * 32 + tx;        // 0..255
    const int x0 = blockIdx.x * TILE_W;
    const int y0 = blockIdx.y * TILE_H;

    const float* __restrict__ t0 = tpl;
    const float* __restrict__ t1 = tpl + IMG_H * IMG_W;
    const float* __restrict__ t2 = tpl + 2 * IMG_H * IMG_W;
    const float* __restrict__ v0 = vec;
    const float* __restrict__ v1 = vec + IMG_H * IMG_W;

    // ---- cooperative fill of the haloed region (zero-pad OOB) ----
    // Template planes are stored PRE-SCALED by sqrt(50) so that
    // 50*sum((c-a)^2) == sum((c'-a')^2) in the inner loop.
    #pragma unroll 7
    for (int i = tid; i < NPLANE; i += 256) {
        int rr = i / RW;
        int cc = i - rr * RW;
        int gy = y0 - 2 + rr;
        int gx = x0 - 2 + cc;
        bool inb = ((unsigned)gy < IMG_H) && ((unsigned)gx < IMG_W);
        int g = inb ? (gy * IMG_W + gx) : 0;
        sT0[i] = inb ? (SQ50 * __ldg(t0 + g)) : 0.0f;
        sT1[i] = inb ? (SQ50 * __ldg(t1 + g)) : 0.0f;
        sT2[i] = inb ? (SQ50 * __ldg(t2 + g)) : 0.0f;
        sV0[i] = inb ? __ldg(v0 + g) : 0.0f;
        sV1[i] = inb ? __ldg(v1 + g) : 0.0f;
    }
    __syncthreads();

    // ---- each thread computes 4 consecutive output pixels ----
    const int bcol = tx * 4;                 // smem base col of 8-float window
    const int ccol = bcol + 2;               // smem col of first center pixel

    float c0[4], c1[4], c2[4];               // pre-scaled centers
    #pragma unroll
    for (int p = 0; p < 4; p++) {
        int s = (ty + 2) * RW + ccol + p;
        c0[p] = sT0[s];
        c1[p] = sT1[s];
        c2[p] = sT2[s];
    }

    float num0[4] = {0.f, 0.f, 0.f, 0.f};
    float num1[4] = {0.f, 0.f, 0.f, 0.f};
    float den[4]  = {0.f, 0.f, 0.f, 0.f};

    #pragma unroll
    for (int r = 0; r < 5; r++) {            // tap row: dy = r - 2
        const int base = (ty + r) * RW + bcol;

        float a[8], b[8], c[8], va[8], vb[8];
        *(float4*)&a[0]  = *(const float4*)&sT0[base];
        *(float4*)&a[4]  = *(const float4*)&sT0[base + 4];
        *(float4*)&b[0]  = *(const float4*)&sT1[base];
        *(float4*)&b[4]  = *(const float4*)&sT1[base + 4];
        *(float4*)&c[0]  = *(const float4*)&sT2[base];
        *(float4*)&c[4]  = *(const float4*)&sT2[base + 4];
        *(float4*)&va[0] = *(const float4*)&sV0[base];
        *(float4*)&va[4] = *(const float4*)&sV0[base + 4];
        *(float4*)&vb[0] = *(const float4*)&sV1[base];
        *(float4*)&vb[4] = *(const float4*)&sV1[base + 4];

        #pragma unroll
        for (int dx = 0; dx < 5; dx++) {
            #pragma unroll
            for (int p = 0; p < 4; p++) {
                const int j = dx + p;
                float d0 = c0[p] - a[j];
                float d1 = c1[p] - b[j];
                float d2 = c2[p] - c[j];
                // w = max(0.875 - (d0^2 + d1^2 + d2^2), 0)   [inputs pre-scaled]
                float w = fmaf(d0, -d0, 0.875f);
                w = fmaf(d1, -d1, w);
                w = fmaf(d2, -d2, w);
                w = fmaxf(w, 0.0f);
                den[p]  += w;
                num0[p]  = fmaf(w, va[j], num0[p]);
                num1[p]  = fmaf(w, vb[j], num1[p]);
            }
        }
    }

    // ---- normalize and store as float32, 16B coalesced per plane ----
    const int gy = y0 + ty;
    const int gx = x0 + bcol;

    float4 r0, r1;
    {
        float inv0 = 1.0f / den[0];
        float inv1 = 1.0f / den[1];
        float inv2 = 1.0f / den[2];
        float inv3 = 1.0f / den[3];
        r0 = make_float4(num0[0] * inv0, num0[1] * inv1, num0[2] * inv2, num0[3] * inv3);
        r1 = make_float4(num1[0] * inv0, num1[1] * inv1, num1[2] * inv2, num1[3] * inv3);
    }

    *reinterpret_cast<float4*>(out + (size_t)gy * IMG_W + gx) = r0;
    *reinterpret_cast<float4*>(out + (size_t)IMG_H * IMG_W + (size_t)gy * IMG_W + gx) = r1;
}

extern "C" void kernel_launch(void* const* d_in, const int* in_sizes, int n_in,
                              void* d_out, int out_size)
{
    // Bind by size: largest = template (3*H*W), second-largest = vector (2*H*W).
    int big0 = -1, big1 = -1;
    for (int i = 0; i < n_in; i++) {
        if (big0 < 0 || in_sizes[i] > in_sizes[big0]) { big1 = big0; big0 = i; }
        else if (big1 < 0 || in_sizes[i] > in_sizes[big1]) { big1 = i; }
    }
    if (big1 < 0) big1 = big0;

    const float* tpl = (const float*)d_in[big0];
    const float* vec = (const float*)d_in[big1];
    float* out = (float*)d_out;               // OUTPUT IS FLOAT32

    dim3 block(32, 8);
    dim3 grid(IMG_W / TILE_W, IMG_H / TILE_H);  // 15 x 135, exact tiling
    jbf_kernel<<<grid, block>>>(tpl, vec, out);
}